// round 15
// baseline (speedup 1.0000x reference)
#include <cuda_runtime.h>
#include <cuda_bf16.h>
#include <cstdint>

#define N_NODES 100000
#define N_EDGES 600000
#define F_IN 128
#define HID 128
#define CLS 16

// ---------------- scratch (device globals: no allocation allowed) ----------
__device__ float g_deg[N_NODES];                          // in-degree (float)
__device__ float4 g_agg4[(size_t)N_NODES * F_IN / 4];     // layer-1 neighbor sum
__device__ float4 g_h4[(size_t)N_NODES * HID / 4];        // layer-1 output
__device__ float4 g_t4[(size_t)N_NODES * CLS / 4];        // h @ W2_l (pre-aggregation)
__device__ float4 g_agg24[(size_t)N_NODES * CLS / 4];     // layer-2 neighbor sum of t
__device__ int g_src[N_EDGES];
__device__ int g_dst[N_EDGES];
__device__ int g_fmt64;                                    // 1 if edge_index is int64
// bf16 hi/lo images of W1l/W1r as B[n][k] (k contiguous = col-major for mma.sync)
__device__ __align__(16) uint16_t g_Bh_img[2][128 * 128];
__device__ __align__(16) uint16_t g_Bl_img[2][128 * 128];

#define g_h    ((float*)g_h4)
#define g_t    ((float*)g_t4)
#define g_agg2 ((float*)g_agg24)

// ---------------- mma.sync helpers (portable sm_80+ HMMA path) --------------
__device__ __forceinline__ void mma_bf16(float* d, const uint32_t* a,
                                         const uint32_t* b) {
    asm volatile(
        "mma.sync.aligned.m16n8k16.row.col.f32.bf16.bf16.f32 "
        "{%0,%1,%2,%3}, {%4,%5,%6,%7}, {%8,%9}, {%0,%1,%2,%3};"
        : "+f"(d[0]), "+f"(d[1]), "+f"(d[2]), "+f"(d[3])
        : "r"(a[0]), "r"(a[1]), "r"(a[2]), "r"(a[3]), "r"(b[0]), "r"(b[1]));
}
__device__ __forceinline__ void ldsm4(uint32_t* r, uint32_t addr) {
    asm volatile(
        "ldmatrix.sync.aligned.m8n8.x4.shared.b16 {%0,%1,%2,%3}, [%4];"
        : "=r"(r[0]), "=r"(r[1]), "=r"(r[2]), "=r"(r[3]) : "r"(addr));
}
__device__ __forceinline__ uint32_t smem_u32(const void* p) {
    uint32_t a;
    asm("{ .reg .u64 t; cvta.to.shared.u64 t, %1; cvt.u32.u64 %0, t; }"
        : "=r"(a) : "l"(p));
    return a;
}

// smem layout (64-row gemm CTA, 2 CTAs/SM):
// A panels 64x136 bf16 (hi, lo), B panels 128x136 bf16 (hi, lo)
#define PADK 136
#define ROWB (PADK * 2)            // 272 bytes per row
#define ASZ_A (64 * ROWB)          // 17408 bytes
#define ASZ_B (128 * ROWB)         // 34816 bytes
#define OFF_AH 0
#define OFF_AL (ASZ_A)
#define OFF_BH (2 * ASZ_A)
#define OFF_BL (2 * ASZ_A + ASZ_B)
#define SMEM_G1 (2 * ASZ_A + 2 * ASZ_B)   // 104448 bytes -> 2 CTAs/SM

#define NGB 1563                   // gemm blocks: 1563*64 >= 100000
#define EPB 384                    // edges per scatter block (1563*384 >= 600000)

// ---------------- kernel 0a: detect edge_index dtype ------------------------
__global__ void detect_kernel(const int* __restrict__ ew) {
    __shared__ int sacc[256];
    int acc = 0;
    for (int i = threadIdx.x; i < 4096; i += 256)
        acc |= ew[2 * i + 1];
    sacc[threadIdx.x] = acc;
    __syncthreads();
    if (threadIdx.x == 0) {
        int t = 0;
        for (int i = 0; i < 256; i++) t |= sacc[i];
        g_fmt64 = (t == 0) ? 1 : 0;
    }
}

// ---------------- kernel 0b: decode edge list to int32 src/dst --------------
__global__ void __launch_bounds__(256)
decode_kernel(const int* __restrict__ ew) {
    int e = blockIdx.x * blockDim.x + threadIdx.x;
    if (e >= N_EDGES) return;
    if (g_fmt64) {
        g_src[e] = ew[2 * e];
        g_dst[e] = ew[2 * (N_EDGES + e)];
    } else {
        g_src[e] = ew[e];
        g_dst[e] = ew[N_EDGES + e];
    }
}

// ---------------- kernel 0c: convert W1l/W1r -> bf16 hi/lo B[n][k] ----------
__global__ void __launch_bounds__(256)
wconv_kernel(const float* __restrict__ W1l, const float* __restrict__ W1r) {
    int id = blockIdx.x * blockDim.x + threadIdx.x;
    if (id >= 2 * 128 * 128) return;
    int p = id >> 14, rem = id & 16383;
    int n = rem >> 7, k = rem & 127;
    const float* W = p ? W1r : W1l;
    float w = W[k * 128 + n];                 // W[k][n] -> B[n][k]
    __nv_bfloat16 h = __float2bfloat16(w);
    __nv_bfloat16 l = __float2bfloat16(w - __bfloat162float(h));
    g_Bh_img[p][n * 128 + k] = *(uint16_t*)&h;
    g_Bl_img[p][n * 128 + k] = *(uint16_t*)&l;
}

// ---------------- fused kernel A: scatter (odd blocks) + x@W1r (even) -------
// Even blocks: 64x128 mma tile of P1 = x @ W1r, stored RAW fp32 to g_h.
// Odd blocks: 384 edges each, 8-edge prefetch batches per warp; float4 vector
// atomics into g_agg + float deg atomics. Roles interleave across SMs so the
// LTS-bound scatter overlaps the tensor-bound GEMM.
__global__ void __launch_bounds__(256, 2)
megaA_kernel(const float* __restrict__ x) {
    extern __shared__ __align__(16) char sm[];
    int tid = threadIdx.x, wid = tid >> 5, lane = tid & 31;

    if (blockIdx.x & 1) {
        // ---------------- scatter role ----------------
        int sb = blockIdx.x >> 1;
        int base = sb * EPB + wid * (EPB / 8);   // 48 edges per warp
#pragma unroll 1
        for (int j0 = 0; j0 < EPB / 8; j0 += 8) {
            int e0 = base + j0;
            int idx = -1;
            if (lane < 8) {
                int e = e0 + lane;
                if (e < N_EDGES) idx = g_src[e];
            } else if (lane < 16) {
                int e = e0 + lane - 8;
                if (e < N_EDGES) idx = g_dst[e];
            }
            int ss[8], dd[8];
#pragma unroll
            for (int t = 0; t < 8; t++) {
                ss[t] = __shfl_sync(0xffffffffu, idx, t);
                dd[t] = __shfl_sync(0xffffffffu, idx, 8 + t);
            }
            float4 v[8];
#pragma unroll
            for (int t = 0; t < 8; t++)
                if (ss[t] >= 0)
                    v[t] = ((const float4*)x)[(size_t)ss[t] * 32 + lane];
#pragma unroll
            for (int t = 0; t < 8; t++)
                if (ss[t] >= 0) {
                    atomicAdd(&g_agg4[(size_t)dd[t] * 32 + lane], v[t]);
                    if (lane == 0) atomicAdd(&g_deg[dd[t]], 1.0f);
                }
        }
        return;
    }

    // ---------------- gemm role: P1 = x @ W1r ----------------
    int gb = blockIdx.x >> 1;
    int row0 = gb * 64;
    int qr = lane >> 2, qc = lane & 3;
    int r0 = (wid & 3) * 16;
    int c0 = (wid >> 2) * 64;

    uint32_t smb = smem_u32(sm);
    uint32_t a_base = smb +
        (uint32_t)((r0 + ((lane >> 3) & 1) * 8 + (lane & 7)) * ROWB
                   + ((lane >> 4) & 1) * 16);
    uint32_t b_base[4];
#pragma unroll
    for (int p = 0; p < 4; p++)
        b_base[p] = smb +
            (uint32_t)((c0 + 16 * p + ((lane >> 4) & 1) * 8 + (lane & 7)) * ROWB
                       + ((lane >> 3) & 1) * 16);

    // A conversion: x rows -> bf16 hi/lo panels
    for (int f = tid; f < 64 * 32; f += 256) {
        int r = f >> 5, q = f & 31;
        int gi = row0 + r;
        float4 v = make_float4(0.f, 0.f, 0.f, 0.f);
        if (gi < N_NODES) v = ((const float4*)(x + (size_t)gi * 128))[q];
        __nv_bfloat16 h0 = __float2bfloat16(v.x), h1 = __float2bfloat16(v.y);
        __nv_bfloat16 h2 = __float2bfloat16(v.z), h3 = __float2bfloat16(v.w);
        __nv_bfloat16 l0 = __float2bfloat16(v.x - __bfloat162float(h0));
        __nv_bfloat16 l1 = __float2bfloat16(v.y - __bfloat162float(h1));
        __nv_bfloat16 l2 = __float2bfloat16(v.z - __bfloat162float(h2));
        __nv_bfloat16 l3 = __float2bfloat16(v.w - __bfloat162float(h3));
        uint64_t hp = (uint64_t)(*(uint16_t*)&h0)
                    | ((uint64_t)(*(uint16_t*)&h1) << 16)
                    | ((uint64_t)(*(uint16_t*)&h2) << 32)
                    | ((uint64_t)(*(uint16_t*)&h3) << 48);
        uint64_t lp = (uint64_t)(*(uint16_t*)&l0)
                    | ((uint64_t)(*(uint16_t*)&l1) << 16)
                    | ((uint64_t)(*(uint16_t*)&l2) << 32)
                    | ((uint64_t)(*(uint16_t*)&l3) << 48);
        int off = r * ROWB + q * 8;
        *(uint64_t*)(sm + OFF_AH + off) = hp;
        *(uint64_t*)(sm + OFF_AL + off) = lp;
    }
    // B copy: W1r images (index 1)
    for (int i = tid; i < 2048; i += 256) {
        int r = i >> 4, w = i & 15;
        int dst = r * ROWB + w * 16;
        *(float4*)(sm + OFF_BH + dst) = ((const float4*)g_Bh_img[1])[i];
        *(float4*)(sm + OFF_BL + dst) = ((const float4*)g_Bl_img[1])[i];
    }
    __syncthreads();

    float d[8][4];
#pragma unroll
    for (int nj = 0; nj < 8; nj++)
#pragma unroll
        for (int v = 0; v < 4; v++) d[nj][v] = 0.f;

#pragma unroll 1
    for (int ks = 0; ks < 8; ks++) {
        uint32_t kadv = (uint32_t)(ks * 32);
        uint32_t ah[4], al[4];
        ldsm4(ah, a_base + OFF_AH + kadv);
        ldsm4(al, a_base + OFF_AL + kadv);
        uint32_t bh[4][4], bl[4][4];
#pragma unroll
        for (int p = 0; p < 4; p++) {
            ldsm4(bh[p], b_base[p] + OFF_BH + kadv);
            ldsm4(bl[p], b_base[p] + OFF_BL + kadv);
        }
#pragma unroll
        for (int p = 0; p < 4; p++) {
            mma_bf16(d[2 * p],     ah, &bh[p][0]);
            mma_bf16(d[2 * p],     al, &bh[p][0]);
            mma_bf16(d[2 * p],     ah, &bl[p][0]);
            mma_bf16(d[2 * p + 1], ah, &bh[p][2]);
            mma_bf16(d[2 * p + 1], al, &bh[p][2]);
            mma_bf16(d[2 * p + 1], ah, &bl[p][2]);
        }
    }

    // epilogue: store RAW partial sums
    {
        int rlo = row0 + r0 + qr;
        int rhi = rlo + 8;
#pragma unroll
        for (int nj = 0; nj < 8; nj++) {
            int gc = c0 + nj * 8 + 2 * qc;
            if (rlo < N_NODES)
                *(float2*)(g_h + (size_t)rlo * 128 + gc)
                    = make_float2(d[nj][0], d[nj][1]);
            if (rhi < N_NODES)
                *(float2*)(g_h + (size_t)rhi * 128 + gc)
                    = make_float2(d[nj][2], d[nj][3]);
        }
    }
}

// ---------------- kernel B: h = relu((agg*invd)@W1l + P1 + b1) --------------
__global__ void __launch_bounds__(256, 2)
gemm1b_kernel(const float* __restrict__ b1) {
    extern __shared__ __align__(16) char sm[];
    __shared__ float s_bias[128];
    __shared__ float s_invd[64];

    int tid = threadIdx.x, wid = tid >> 5, lane = tid & 31;
    int qr = lane >> 2, qc = lane & 3;
    int row0 = blockIdx.x * 64;
    int r0 = (wid & 3) * 16;
    int c0 = (wid >> 2) * 64;

    if (tid < 128) s_bias[tid] = b1[tid];
    if (tid < 64) {
        int gi = row0 + tid;
        float dg = (gi < N_NODES) ? g_deg[gi] : 1.0f;
        s_invd[tid] = 1.0f / fmaxf(dg, 1.0f);
    }
    __syncthreads();

    uint32_t smb = smem_u32(sm);
    uint32_t a_base = smb +
        (uint32_t)((r0 + ((lane >> 3) & 1) * 8 + (lane & 7)) * ROWB
                   + ((lane >> 4) & 1) * 16);
    uint32_t b_base[4];
#pragma unroll
    for (int p = 0; p < 4; p++)
        b_base[p] = smb +
            (uint32_t)((c0 + 16 * p + ((lane >> 4) & 1) * 8 + (lane & 7)) * ROWB
                       + ((lane >> 3) & 1) * 16);

    // A conversion: (agg * invd) -> bf16 hi/lo panels
    for (int f = tid; f < 64 * 32; f += 256) {
        int r = f >> 5, q = f & 31;
        int gi = row0 + r;
        float4 v = make_float4(0.f, 0.f, 0.f, 0.f);
        if (gi < N_NODES) {
            v = g_agg4[(size_t)gi * 32 + q];
            float s = s_invd[r];
            v.x *= s; v.y *= s; v.z *= s; v.w *= s;
        }
        __nv_bfloat16 h0 = __float2bfloat16(v.x), h1 = __float2bfloat16(v.y);
        __nv_bfloat16 h2 = __float2bfloat16(v.z), h3 = __float2bfloat16(v.w);
        __nv_bfloat16 l0 = __float2bfloat16(v.x - __bfloat162float(h0));
        __nv_bfloat16 l1 = __float2bfloat16(v.y - __bfloat162float(h1));
        __nv_bfloat16 l2 = __float2bfloat16(v.z - __bfloat162float(h2));
        __nv_bfloat16 l3 = __float2bfloat16(v.w - __bfloat162float(h3));
        uint64_t hp = (uint64_t)(*(uint16_t*)&h0)
                    | ((uint64_t)(*(uint16_t*)&h1) << 16)
                    | ((uint64_t)(*(uint16_t*)&h2) << 32)
                    | ((uint64_t)(*(uint16_t*)&h3) << 48);
        uint64_t lp = (uint64_t)(*(uint16_t*)&l0)
                    | ((uint64_t)(*(uint16_t*)&l1) << 16)
                    | ((uint64_t)(*(uint16_t*)&l2) << 32)
                    | ((uint64_t)(*(uint16_t*)&l3) << 48);
        int off = r * ROWB + q * 8;
        *(uint64_t*)(sm + OFF_AH + off) = hp;
        *(uint64_t*)(sm + OFF_AL + off) = lp;
    }
    // B copy: W1l images (index 0)
    for (int i = tid; i < 2048; i += 256) {
        int r = i >> 4, w = i & 15;
        int dst = r * ROWB + w * 16;
        *(float4*)(sm + OFF_BH + dst) = ((const float4*)g_Bh_img[0])[i];
        *(float4*)(sm + OFF_BL + dst) = ((const float4*)g_Bl_img[0])[i];
    }
    __syncthreads();

    float d[8][4];
#pragma unroll
    for (int nj = 0; nj < 8; nj++)
#pragma unroll
        for (int v = 0; v < 4; v++) d[nj][v] = 0.f;

#pragma unroll 1
    for (int ks = 0; ks < 8; ks++) {
        uint32_t kadv = (uint32_t)(ks * 32);
        uint32_t ah[4], al[4];
        ldsm4(ah, a_base + OFF_AH + kadv);
        ldsm4(al, a_base + OFF_AL + kadv);
        uint32_t bh[4][4], bl[4][4];
#pragma unroll
        for (int p = 0; p < 4; p++) {
            ldsm4(bh[p], b_base[p] + OFF_BH + kadv);
            ldsm4(bl[p], b_base[p] + OFF_BL + kadv);
        }
#pragma unroll
        for (int p = 0; p < 4; p++) {
            mma_bf16(d[2 * p],     ah, &bh[p][0]);
            mma_bf16(d[2 * p],     al, &bh[p][0]);
            mma_bf16(d[2 * p],     ah, &bl[p][0]);
            mma_bf16(d[2 * p + 1], ah, &bh[p][2]);
            mma_bf16(d[2 * p + 1], al, &bh[p][2]);
            mma_bf16(d[2 * p + 1], ah, &bl[p][2]);
        }
    }

    // epilogue: add raw P1 + bias, relu, store
    {
        int rlo = row0 + r0 + qr;
        int rhi = rlo + 8;
#pragma unroll
        for (int nj = 0; nj < 8; nj++) {
            int gc = c0 + nj * 8 + 2 * qc;
            float b0v = s_bias[gc], b1v = s_bias[gc + 1];
            if (rlo < N_NODES) {
                float2 pv = *(float2*)(g_h + (size_t)rlo * 128 + gc);
                float2 o;
                o.x = fmaxf(d[nj][0] + pv.x + b0v, 0.f);
                o.y = fmaxf(d[nj][1] + pv.y + b1v, 0.f);
                *(float2*)(g_h + (size_t)rlo * 128 + gc) = o;
            }
            if (rhi < N_NODES) {
                float2 pv = *(float2*)(g_h + (size_t)rhi * 128 + gc);
                float2 o;
                o.x = fmaxf(d[nj][2] + pv.x + b0v, 0.f);
                o.y = fmaxf(d[nj][3] + pv.y + b1v, 0.f);
                *(float2*)(g_h + (size_t)rhi * 128 + gc) = o;
            }
        }
    }
}

// ---------------- kernel 3: t = h@W2l (-> g_t), r = h@W2r (-> d_out staging) -
__global__ void __launch_bounds__(256)
gemm2_kernel(const float* __restrict__ W2l, const float* __restrict__ W2r,
             float* __restrict__ outr) {
    __shared__ float Wsh[128 * 32];
    __shared__ float Ash[64 * 128];
    int tid = threadIdx.x;
    int row0 = blockIdx.x * 64;

    for (int i = tid; i < 128 * 16; i += 256) {
        int k = i >> 4, c = i & 15;
        Wsh[k * 32 + c]      = W2l[i];
        Wsh[k * 32 + 16 + c] = W2r[i];
    }
    for (int idx = tid; idx < 64 * 32; idx += 256) {   // float4 units
        int r = idx >> 5, q = idx & 31;
        int gi = row0 + r;
        float4 v = (gi < N_NODES) ? g_h4[(size_t)gi * 32 + q]
                                  : make_float4(0.f, 0.f, 0.f, 0.f);
        ((float4*)(Ash + r * 128))[q] = v;
    }
    __syncthreads();

    int warp = tid >> 5, lane = tid & 31;
    int r0 = warp * 8;
    float acc[8] = {0.f, 0.f, 0.f, 0.f, 0.f, 0.f, 0.f, 0.f};

    for (int k = 0; k < 128; k += 4) {
        float4 a4[8];
#pragma unroll
        for (int r = 0; r < 8; r++)
            a4[r] = *(const float4*)(Ash + (r0 + r) * 128 + k);
#pragma unroll
        for (int kk = 0; kk < 4; kk++) {
            float w = Wsh[(k + kk) * 32 + lane];
#pragma unroll
            for (int r = 0; r < 8; r++) {
                float a = (kk == 0) ? a4[r].x : (kk == 1) ? a4[r].y
                         : (kk == 2) ? a4[r].z : a4[r].w;
                acc[r] = fmaf(a, w, acc[r]);
            }
        }
    }
#pragma unroll
    for (int r = 0; r < 8; r++) {
        int gi = row0 + r0 + r;
        if (gi >= N_NODES) continue;
        if (lane < 16) g_t[(size_t)gi * CLS + lane] = acc[r];
        else           outr[(size_t)gi * CLS + (lane - 16)] = acc[r];
    }
}

// ---------------- kernel 4: scatter t[src] -> agg2[dst] (16 floats/edge) ----
__global__ void __launch_bounds__(256)
scatter2_kernel() {
    int idx = blockIdx.x * blockDim.x + threadIdx.x;
    int e = idx >> 2;
    if (e >= N_EDGES) return;
    int l = idx & 3;
    int s = g_src[e];
    int d = g_dst[e];
    float4 v = g_t4[(size_t)s * (CLS / 4) + l];
    atomicAdd(&g_agg24[(size_t)d * (CLS / 4) + l], v);
}

// ---------------- kernel 5: out = log_softmax(r + b2 + agg2/deg) ------------
__global__ void __launch_bounds__(256)
final_kernel(float* __restrict__ out, const float* __restrict__ b2) {
    int idx = blockIdx.x * blockDim.x + threadIdx.x;
    int row = idx >> 4;
    int c = idx & 15;
    if (row >= N_NODES) return;
    float invd = 1.0f / fmaxf(g_deg[row], 1.0f);
    float v = out[(size_t)row * CLS + c] + b2[c]
            + g_agg2[(size_t)row * CLS + c] * invd;
    float m = v;
#pragma unroll
    for (int o = 8; o > 0; o >>= 1)
        m = fmaxf(m, __shfl_xor_sync(0xffffffffu, m, o, 16));
    float e = __expf(v - m);
    float ssum = e;
#pragma unroll
    for (int o = 8; o > 0; o >>= 1)
        ssum += __shfl_xor_sync(0xffffffffu, ssum, o, 16);
    out[(size_t)row * CLS + c] = v - m - __logf(ssum);
}

// ---------------- launch ----------------------------------------------------
extern "C" void kernel_launch(void* const* d_in, const int* in_sizes, int n_in,
                              void* d_out, int out_size) {
    const float* x   = (const float*)d_in[0];
    const int*   ew  = (const int*)d_in[1];      // edge_index raw 32-bit words
    const float* W1l = (const float*)d_in[2];
    const float* b1  = (const float*)d_in[3];
    const float* W1r = (const float*)d_in[4];
    const float* W2l = (const float*)d_in[5];
    const float* b2  = (const float*)d_in[6];
    const float* W2r = (const float*)d_in[7];
    float* out = (float*)d_out;

    void *p_deg, *p_agg, *p_agg2;
    cudaGetSymbolAddress(&p_deg,  g_deg);
    cudaGetSymbolAddress(&p_agg,  g_agg4);
    cudaGetSymbolAddress(&p_agg2, g_agg24);
    cudaMemsetAsync(p_deg,  0, sizeof(float) * N_NODES);
    cudaMemsetAsync(p_agg,  0, sizeof(float) * (size_t)N_NODES * F_IN);
    cudaMemsetAsync(p_agg2, 0, sizeof(float) * (size_t)N_NODES * CLS);

    detect_kernel<<<1, 256>>>(ew);
    decode_kernel<<<(N_EDGES + 255) / 256, 256>>>(ew);
    wconv_kernel<<<(2 * 128 * 128 + 255) / 256, 256>>>(W1l, W1r);

    cudaFuncSetAttribute(megaA_kernel, cudaFuncAttributeMaxDynamicSharedMemorySize,
                         SMEM_G1);
    cudaFuncSetAttribute(gemm1b_kernel, cudaFuncAttributeMaxDynamicSharedMemorySize,
                         SMEM_G1);

    megaA_kernel<<<2 * NGB, 256, SMEM_G1>>>(x);
    gemm1b_kernel<<<NGB, 256, SMEM_G1>>>(b1);

    gemm2_kernel<<<(N_NODES + 63) / 64, 256>>>(W2l, W2r, out);

    scatter2_kernel<<<(N_EDGES * 4 + 255) / 256, 256>>>();

    final_kernel<<<(N_NODES * CLS) / 256, 256>>>(out, b2);
}

// round 16
// speedup vs baseline: 1.3310x; 1.3310x over previous
#include <cuda_runtime.h>
#include <cuda_bf16.h>
#include <cstdint>

#define N_NODES 100000
#define N_EDGES 600000
#define F_IN 128
#define HID 128
#define CLS 16

// ---------------- scratch (device globals: no allocation allowed) ----------
__device__ float4 g_deg4[(N_NODES + 3) / 4];              // in-degree (float)
__device__ float4 g_agg4[(size_t)N_NODES * F_IN / 4];     // layer-1 neighbor sum
__device__ float4 g_h4[(size_t)N_NODES * HID / 4];        // layer-1 output
__device__ float4 g_t4[(size_t)N_NODES * CLS / 4];        // h @ W2_l (pre-aggregation)
__device__ float4 g_agg24[(size_t)N_NODES * CLS / 4];     // layer-2 neighbor sum of t
__device__ int g_src[N_EDGES];
__device__ int g_dst[N_EDGES];
// bf16 hi/lo images of W1l/W1r as B[n][k] (k contiguous = col-major for mma.sync)
__device__ __align__(16) uint16_t g_Bh_img[2][128 * 128];
__device__ __align__(16) uint16_t g_Bl_img[2][128 * 128];

#define g_deg  ((float*)g_deg4)
#define g_h    ((float*)g_h4)
#define g_t    ((float*)g_t4)
#define g_agg2 ((float*)g_agg24)

// ---------------- helpers ----------------------------------------------------
__device__ __forceinline__ void mma_bf16(float* d, const uint32_t* a,
                                         const uint32_t* b) {
    asm volatile(
        "mma.sync.aligned.m16n8k16.row.col.f32.bf16.bf16.f32 "
        "{%0,%1,%2,%3}, {%4,%5,%6,%7}, {%8,%9}, {%0,%1,%2,%3};"
        : "+f"(d[0]), "+f"(d[1]), "+f"(d[2]), "+f"(d[3])
        : "r"(a[0]), "r"(a[1]), "r"(a[2]), "r"(a[3]), "r"(b[0]), "r"(b[1]));
}
__device__ __forceinline__ void ldsm4(uint32_t* r, uint32_t addr) {
    asm volatile(
        "ldmatrix.sync.aligned.m8n8.x4.shared.b16 {%0,%1,%2,%3}, [%4];"
        : "=r"(r[0]), "=r"(r[1]), "=r"(r[2]), "=r"(r[3]) : "r"(addr));
}
__device__ __forceinline__ uint32_t smem_u32(const void* p) {
    uint32_t a;
    asm("{ .reg .u64 t; cvta.to.shared.u64 t, %1; cvt.u32.u64 %0, t; }"
        : "=r"(a) : "l"(p));
    return a;
}
__device__ __forceinline__ unsigned long long pack2(float a, float b) {
    unsigned long long r;
    asm("mov.b64 %0, {%1, %2};" : "=l"(r) : "f"(a), "f"(b));
    return r;
}
__device__ __forceinline__ unsigned long long pack_dup(float a) {
    unsigned long long r;
    asm("mov.b64 %0, {%1, %1};" : "=l"(r) : "f"(a));
    return r;
}
__device__ __forceinline__ void unpack2(unsigned long long v, float& a, float& b) {
    asm("mov.b64 {%0, %1}, %2;" : "=f"(a), "=f"(b) : "l"(v));
}
__device__ __forceinline__ void fma2(unsigned long long& d, unsigned long long a,
                                     unsigned long long b) {
    asm("fma.rn.f32x2 %0, %1, %2, %0;" : "+l"(d) : "l"(a), "l"(b));
}

// smem layout for gemm1 (64-row CTA, 2 CTAs/SM)
#define PADK 136
#define ROWB (PADK * 2)            // 272 bytes per row
#define ASZ_A (64 * ROWB)          // 17408 bytes
#define ASZ_B (128 * ROWB)         // 34816 bytes
#define OFF_AH 0
#define OFF_AL (ASZ_A)
#define OFF_BH (2 * ASZ_A)
#define OFF_BL (2 * ASZ_A + ASZ_B)
#define SMEM_G1 (2 * ASZ_A + 2 * ASZ_B)   // 104448 bytes -> 2 CTAs/SM

// prep kernel block roles
#define NB_DEC 2344                          // decode: 2344*256 >= 600000
#define NZ_F4  (3200000 + 400000 + 25000)    // agg + agg2 + deg in float4 units
#define NB_ZERO ((NZ_F4 + 4095) / 4096)      // 886 blocks, 16 f4/thread
#define NB_WCONV 128                         // 32768 weight elems
#define NB_PREP (NB_DEC + NB_ZERO + NB_WCONV)

// ---------------- kernel 0: decode(+detect) | zero scratch | wconv ----------
__global__ void __launch_bounds__(256)
prep_kernel(const int* __restrict__ ew,
            const float* __restrict__ W1l, const float* __restrict__ W1r) {
    int b = blockIdx.x, tid = threadIdx.x;
    if (b < NB_DEC) {
        // decode with per-block format detection: int64 layout => odd words all 0
        int e = b * 256 + tid;
        int odd = (e < N_EDGES) ? ew[2 * e + 1] : 0;
        int is32 = __syncthreads_or(odd != 0);
        if (e < N_EDGES) {
            if (is32) {
                g_src[e] = ew[e];
                g_dst[e] = ew[N_EDGES + e];
            } else {
                g_src[e] = ew[2 * e];
                g_dst[e] = ew[2 * (N_EDGES + e)];
            }
        }
        return;
    }
    if (b < NB_DEC + NB_ZERO) {
        int base = (b - NB_DEC) * 4096 + tid;
        float4 z = make_float4(0.f, 0.f, 0.f, 0.f);
#pragma unroll
        for (int w = 0; w < 16; w++) {
            int i = base + w * 256;
            if (i < 3200000)           g_agg4[i] = z;
            else if (i < 3600000)      g_agg24[i - 3200000] = z;
            else if (i < NZ_F4)        g_deg4[i - 3600000] = z;
        }
        return;
    }
    // wconv role
    int id = (b - NB_DEC - NB_ZERO) * 256 + tid;
    if (id >= 2 * 128 * 128) return;
    int p = id >> 14, rem = id & 16383;
    int n = rem >> 7, k = rem & 127;
    const float* W = p ? W1r : W1l;
    float w = W[k * 128 + n];                 // W[k][n] -> B[n][k]
    __nv_bfloat16 h = __float2bfloat16(w);
    __nv_bfloat16 l = __float2bfloat16(w - __bfloat162float(h));
    g_Bh_img[p][n * 128 + k] = *(uint16_t*)&h;
    g_Bl_img[p][n * 128 + k] = *(uint16_t*)&l;
}

// ---------------- kernel 1: batched scatter x[src] -> agg[dst], deg++ -------
// one warp per 8 edges: 8 gathers in flight per warp, then vector-atomic adds
__global__ void __launch_bounds__(256)
scatter1_kernel(const float* __restrict__ x) {
    int gw = (blockIdx.x * 256 + threadIdx.x) >> 5;
    int lane = threadIdx.x & 31;
    int e0 = gw * 8;
    if (e0 >= N_EDGES) return;
    int idx = -1;
    if (lane < 8) {
        int e = e0 + lane;
        if (e < N_EDGES) idx = g_src[e];
    } else if (lane < 16) {
        int e = e0 + lane - 8;
        if (e < N_EDGES) idx = g_dst[e];
    }
    int ss[8], dd[8];
#pragma unroll
    for (int t = 0; t < 8; t++) {
        ss[t] = __shfl_sync(0xffffffffu, idx, t);
        dd[t] = __shfl_sync(0xffffffffu, idx, 8 + t);
    }
    float4 v[8];
#pragma unroll
    for (int t = 0; t < 8; t++)
        if (ss[t] >= 0)
            v[t] = ((const float4*)x)[(size_t)ss[t] * 32 + lane];
#pragma unroll
    for (int t = 0; t < 8; t++)
        if (ss[t] >= 0) {
            atomicAdd(&g_agg4[(size_t)dd[t] * 32 + lane], v[t]);
            if (lane == t) atomicAdd(&g_deg[dd[t]], 1.0f);
        }
}

// ---------------- kernel 2: h = relu((agg*invd)@W1l + b1 + x@W1r) -----------
// mma.sync bf16 3-term split GEMM. CTA = 64x128 tile, 2 CTAs/SM, ldmatrix.
__global__ void __launch_bounds__(256, 2)
gemm1_kernel(const float* __restrict__ x, const float* __restrict__ b1) {
    extern __shared__ __align__(16) char sm[];
    __shared__ float s_bias[128];
    __shared__ float s_invd[64];

    int tid = threadIdx.x, wid = tid >> 5, lane = tid & 31;
    int qr = lane >> 2, qc = lane & 3;
    int row0 = blockIdx.x * 64;
    int r0 = (wid & 3) * 16;
    int c0 = (wid >> 2) * 64;

    if (tid < 128) s_bias[tid] = b1[tid];
    if (tid < 64) {
        int gi = row0 + tid;
        float dg = (gi < N_NODES) ? g_deg[gi] : 1.0f;
        s_invd[tid] = 1.0f / fmaxf(dg, 1.0f);
    }

    uint32_t smb = smem_u32(sm);
    uint32_t a_base = smb +
        (uint32_t)((r0 + ((lane >> 3) & 1) * 8 + (lane & 7)) * ROWB
                   + ((lane >> 4) & 1) * 16);
    uint32_t b_base[4];
#pragma unroll
    for (int p = 0; p < 4; p++)
        b_base[p] = smb +
            (uint32_t)((c0 + 16 * p + ((lane >> 4) & 1) * 8 + (lane & 7)) * ROWB
                       + ((lane >> 3) & 1) * 16);

    float d[8][4];
#pragma unroll
    for (int nj = 0; nj < 8; nj++)
#pragma unroll
        for (int v = 0; v < 4; v++) d[nj][v] = 0.f;

#pragma unroll 1
    for (int phase = 0; phase < 2; phase++) {
        __syncthreads();

        for (int f = tid; f < 64 * 32; f += 256) {
            int r = f >> 5, q = f & 31;
            int gi = row0 + r;
            float4 v = make_float4(0.f, 0.f, 0.f, 0.f);
            if (gi < N_NODES) {
                if (phase == 0) {
                    v = g_agg4[(size_t)gi * 32 + q];
                    float s = s_invd[r];
                    v.x *= s; v.y *= s; v.z *= s; v.w *= s;
                } else {
                    v = ((const float4*)(x + (size_t)gi * 128))[q];
                }
            }
            __nv_bfloat16 h0 = __float2bfloat16(v.x), h1 = __float2bfloat16(v.y);
            __nv_bfloat16 h2 = __float2bfloat16(v.z), h3 = __float2bfloat16(v.w);
            __nv_bfloat16 l0 = __float2bfloat16(v.x - __bfloat162float(h0));
            __nv_bfloat16 l1 = __float2bfloat16(v.y - __bfloat162float(h1));
            __nv_bfloat16 l2 = __float2bfloat16(v.z - __bfloat162float(h2));
            __nv_bfloat16 l3 = __float2bfloat16(v.w - __bfloat162float(h3));
            uint64_t hp = (uint64_t)(*(uint16_t*)&h0)
                        | ((uint64_t)(*(uint16_t*)&h1) << 16)
                        | ((uint64_t)(*(uint16_t*)&h2) << 32)
                        | ((uint64_t)(*(uint16_t*)&h3) << 48);
            uint64_t lp = (uint64_t)(*(uint16_t*)&l0)
                        | ((uint64_t)(*(uint16_t*)&l1) << 16)
                        | ((uint64_t)(*(uint16_t*)&l2) << 32)
                        | ((uint64_t)(*(uint16_t*)&l3) << 48);
            int off = r * ROWB + q * 8;
            *(uint64_t*)(sm + OFF_AH + off) = hp;
            *(uint64_t*)(sm + OFF_AL + off) = lp;
        }
        for (int i = tid; i < 2048; i += 256) {
            int r = i >> 4, w = i & 15;
            int dst = r * ROWB + w * 16;
            *(float4*)(sm + OFF_BH + dst) = ((const float4*)g_Bh_img[phase])[i];
            *(float4*)(sm + OFF_BL + dst) = ((const float4*)g_Bl_img[phase])[i];
        }
        __syncthreads();

#pragma unroll 1
        for (int ks = 0; ks < 8; ks++) {
            uint32_t kadv = (uint32_t)(ks * 32);
            uint32_t ah[4], al[4];
            ldsm4(ah, a_base + OFF_AH + kadv);
            ldsm4(al, a_base + OFF_AL + kadv);
            uint32_t bh[4][4], bl[4][4];
#pragma unroll
            for (int p = 0; p < 4; p++) {
                ldsm4(bh[p], b_base[p] + OFF_BH + kadv);
                ldsm4(bl[p], b_base[p] + OFF_BL + kadv);
            }
#pragma unroll
            for (int p = 0; p < 4; p++) {
                mma_bf16(d[2 * p],     ah, &bh[p][0]);
                mma_bf16(d[2 * p],     al, &bh[p][0]);
                mma_bf16(d[2 * p],     ah, &bl[p][0]);
                mma_bf16(d[2 * p + 1], ah, &bh[p][2]);
                mma_bf16(d[2 * p + 1], al, &bh[p][2]);
                mma_bf16(d[2 * p + 1], ah, &bl[p][2]);
            }
        }
    }

    {
        int rlo = row0 + r0 + qr;
        int rhi = rlo + 8;
#pragma unroll
        for (int nj = 0; nj < 8; nj++) {
            int gc = c0 + nj * 8 + 2 * qc;
            float b0v = s_bias[gc], b1v = s_bias[gc + 1];
            if (rlo < N_NODES) {
                float2 o;
                o.x = fmaxf(d[nj][0] + b0v, 0.f);
                o.y = fmaxf(d[nj][1] + b1v, 0.f);
                *(float2*)(g_h + (size_t)rlo * 128 + gc) = o;
            }
            if (rhi < N_NODES) {
                float2 o;
                o.x = fmaxf(d[nj][2] + b0v, 0.f);
                o.y = fmaxf(d[nj][3] + b1v, 0.f);
                *(float2*)(g_h + (size_t)rhi * 128 + gc) = o;
            }
        }
    }
}

// ---------------- kernel 3: t = h@W2l (-> g_t), r = h@W2r (-> out staging) --
// f32x2 packed FMA. thread = 4 rows x 1 col-pair (16 col-pairs x 16 row-groups).
__global__ void __launch_bounds__(256)
gemm2_kernel(const float* __restrict__ W2l, const float* __restrict__ W2r,
             float* __restrict__ outr) {
    __shared__ float Wsh[128 * 32];
    __shared__ float Ash[64 * 128];
    int tid = threadIdx.x;
    int row0 = blockIdx.x * 64;

    for (int i = tid; i < 128 * 16; i += 256) {
        int k = i >> 4, c = i & 15;
        Wsh[k * 32 + c]      = W2l[i];
        Wsh[k * 32 + 16 + c] = W2r[i];
    }
    for (int idx = tid; idx < 64 * 32; idx += 256) {
        int r = idx >> 5, q = idx & 31;
        int gi = row0 + r;
        float4 v = (gi < N_NODES) ? g_h4[(size_t)gi * 32 + q]
                                  : make_float4(0.f, 0.f, 0.f, 0.f);
        ((float4*)(Ash + r * 128))[q] = v;
    }
    __syncthreads();

    int cp = tid & 15;           // col pair (cols 2cp, 2cp+1)
    int rg = tid >> 4;           // row group 0..15
    int r0 = rg * 4;
    unsigned long long acc2[4] = {0ull, 0ull, 0ull, 0ull};

    for (int k = 0; k < 128; k += 4) {
        float4 a4[4];
#pragma unroll
        for (int r = 0; r < 4; r++)
            a4[r] = *(const float4*)(Ash + (r0 + r) * 128 + k);
#pragma unroll
        for (int kk = 0; kk < 4; kk++) {
            float2 wv = *(const float2*)(Wsh + (k + kk) * 32 + 2 * cp);
            unsigned long long wp = pack2(wv.x, wv.y);
#pragma unroll
            for (int r = 0; r < 4; r++) {
                float a = (kk == 0) ? a4[r].x : (kk == 1) ? a4[r].y
                         : (kk == 2) ? a4[r].z : a4[r].w;
                fma2(acc2[r], pack_dup(a), wp);
            }
        }
    }
#pragma unroll
    for (int r = 0; r < 4; r++) {
        int gi = row0 + r0 + r;
        if (gi >= N_NODES) continue;
        float o0, o1;
        unpack2(acc2[r], o0, o1);
        if (cp < 8) {
            g_t[(size_t)gi * CLS + 2 * cp]     = o0;
            g_t[(size_t)gi * CLS + 2 * cp + 1] = o1;
        } else {
            outr[(size_t)gi * CLS + 2 * cp - 16] = o0;
            outr[(size_t)gi * CLS + 2 * cp - 15] = o1;
        }
    }
}

// ---------------- kernel 4: scatter t[src] -> agg2[dst] (16 floats/edge) ----
__global__ void __launch_bounds__(256)
scatter2_kernel() {
    int idx = blockIdx.x * blockDim.x + threadIdx.x;
    int e = idx >> 2;
    if (e >= N_EDGES) return;
    int l = idx & 3;
    int s = g_src[e];
    int d = g_dst[e];
    float4 v = g_t4[(size_t)s * (CLS / 4) + l];
    atomicAdd(&g_agg24[(size_t)d * (CLS / 4) + l], v);
}

// ---------------- kernel 5: out = log_softmax(r + b2 + agg2/deg) ------------
__global__ void __launch_bounds__(256)
final_kernel(float* __restrict__ out, const float* __restrict__ b2) {
    int idx = blockIdx.x * blockDim.x + threadIdx.x;
    int row = idx >> 4;
    int c = idx & 15;
    if (row >= N_NODES) return;
    float invd = 1.0f / fmaxf(g_deg[row], 1.0f);
    float v = out[(size_t)row * CLS + c] + b2[c]
            + g_agg2[(size_t)row * CLS + c] * invd;
    float m = v;
#pragma unroll
    for (int o = 8; o > 0; o >>= 1)
        m = fmaxf(m, __shfl_xor_sync(0xffffffffu, m, o, 16));
    float e = __expf(v - m);
    float ssum = e;
#pragma unroll
    for (int o = 8; o > 0; o >>= 1)
        ssum += __shfl_xor_sync(0xffffffffu, ssum, o, 16);
    out[(size_t)row * CLS + c] = v - m - __logf(ssum);
}

// ---------------- launch ----------------------------------------------------
extern "C" void kernel_launch(void* const* d_in, const int* in_sizes, int n_in,
                              void* d_out, int out_size) {
    const float* x   = (const float*)d_in[0];
    const int*   ew  = (const int*)d_in[1];      // edge_index raw 32-bit words
    const float* W1l = (const float*)d_in[2];
    const float* b1  = (const float*)d_in[3];
    const float* W1r = (const float*)d_in[4];
    const float* W2l = (const float*)d_in[5];
    const float* b2  = (const float*)d_in[6];
    const float* W2r = (const float*)d_in[7];
    float* out = (float*)d_out;

    prep_kernel<<<NB_PREP, 256>>>(ew, W1l, W1r);

    scatter1_kernel<<<(N_EDGES / 8 + 7) / 8, 256>>>(x);   // 75000 warps / 8 per block

    cudaFuncSetAttribute(gemm1_kernel, cudaFuncAttributeMaxDynamicSharedMemorySize,
                         SMEM_G1);
    gemm1_kernel<<<(N_NODES + 63) / 64, 256, SMEM_G1>>>(x, b1);

    gemm2_kernel<<<(N_NODES + 63) / 64, 256>>>(W2l, W2r, out);

    scatter2_kernel<<<(N_EDGES * 4 + 255) / 256, 256>>>();

    final_kernel<<<(N_NODES * CLS) / 256, 256>>>(out, b2);
}

// round 17
// speedup vs baseline: 1.4527x; 1.0915x over previous
#include <cuda_runtime.h>
#include <cuda_bf16.h>
#include <cstdint>

#define N_NODES 100000
#define N_EDGES 600000
#define F_IN 128
#define HID 128
#define CLS 16

// ---------------- scratch (device globals: no allocation allowed) ----------
__device__ float4 g_deg4[(N_NODES + 3) / 4];              // in-degree (float)
__device__ float4 g_agg4[(size_t)N_NODES * F_IN / 4];     // layer-1 neighbor sum
__device__ float4 g_h4[(size_t)N_NODES * HID / 4];        // layer-1 output
__device__ float4 g_t4[(size_t)N_NODES * CLS / 4];        // h @ W2_l (pre-aggregation)
__device__ float4 g_agg24[(size_t)N_NODES * CLS / 4];     // layer-2 neighbor sum of t
__device__ int g_src[N_EDGES];
__device__ int g_dst[N_EDGES];
// bf16 hi/lo images of W1l/W1r as B[n][k] (k contiguous = col-major for mma.sync)
__device__ __align__(16) uint16_t g_Bh_img[2][128 * 128];
__device__ __align__(16) uint16_t g_Bl_img[2][128 * 128];
// combined [W2l|W2r] image: B2[n][k], n 0..15 = W2l cols, 16..31 = W2r cols
__device__ __align__(16) uint16_t g_B2h_img[32 * 128];
__device__ __align__(16) uint16_t g_B2l_img[32 * 128];

#define g_deg  ((float*)g_deg4)
#define g_h    ((float*)g_h4)
#define g_t    ((float*)g_t4)
#define g_agg2 ((float*)g_agg24)

// ---------------- helpers ----------------------------------------------------
__device__ __forceinline__ void mma_bf16(float* d, const uint32_t* a,
                                         const uint32_t* b) {
    asm volatile(
        "mma.sync.aligned.m16n8k16.row.col.f32.bf16.bf16.f32 "
        "{%0,%1,%2,%3}, {%4,%5,%6,%7}, {%8,%9}, {%0,%1,%2,%3};"
        : "+f"(d[0]), "+f"(d[1]), "+f"(d[2]), "+f"(d[3])
        : "r"(a[0]), "r"(a[1]), "r"(a[2]), "r"(a[3]), "r"(b[0]), "r"(b[1]));
}
__device__ __forceinline__ void ldsm4(uint32_t* r, uint32_t addr) {
    asm volatile(
        "ldmatrix.sync.aligned.m8n8.x4.shared.b16 {%0,%1,%2,%3}, [%4];"
        : "=r"(r[0]), "=r"(r[1]), "=r"(r[2]), "=r"(r[3]) : "r"(addr));
}
__device__ __forceinline__ uint32_t smem_u32(const void* p) {
    uint32_t a;
    asm("{ .reg .u64 t; cvta.to.shared.u64 t, %1; cvt.u32.u64 %0, t; }"
        : "=r"(a) : "l"(p));
    return a;
}

// smem layout for gemm1 (64-row CTA, 2 CTAs/SM)
#define PADK 136
#define ROWB (PADK * 2)            // 272 bytes per row
#define ASZ_A (64 * ROWB)          // 17408 bytes
#define ASZ_B (128 * ROWB)         // 34816 bytes
#define OFF_AH 0
#define OFF_AL (ASZ_A)
#define OFF_BH (2 * ASZ_A)
#define OFF_BL (2 * ASZ_A + ASZ_B)
#define SMEM_G1 (2 * ASZ_A + 2 * ASZ_B)   // 104448 bytes -> 2 CTAs/SM

// smem layout for gemm2 (64-row x 32-col CTA)
#define BSZ2 (32 * ROWB)           // 8704 bytes
#define OFF2_AH 0
#define OFF2_AL (ASZ_A)
#define OFF2_BH (2 * ASZ_A)
#define OFF2_BL (2 * ASZ_A + BSZ2)
#define SMEM_G2 (2 * ASZ_A + 2 * BSZ2)    // 52224 bytes -> 4 CTAs/SM

// prep kernel block roles
#define NB_DEC 2344                          // decode: 2344*256 >= 600000
#define NZ_F4  (3200000 + 400000 + 25000)    // agg + agg2 + deg in float4 units
#define NB_ZERO ((NZ_F4 + 4095) / 4096)      // 886 blocks, 16 f4/thread
#define NB_WCONV 144                         // 32768 W1 + 4096 W2 elems
#define NB_PREP (NB_DEC + NB_ZERO + NB_WCONV)

// ---------------- kernel 0: decode(+detect) | zero scratch | wconv ----------
__global__ void __launch_bounds__(256)
prep_kernel(const int* __restrict__ ew,
            const float* __restrict__ W1l, const float* __restrict__ W1r,
            const float* __restrict__ W2l, const float* __restrict__ W2r) {
    int b = blockIdx.x, tid = threadIdx.x;
    if (b < NB_DEC) {
        // decode with per-block format detection: int64 layout => odd words all 0
        int e = b * 256 + tid;
        int odd = (e < N_EDGES) ? ew[2 * e + 1] : 0;
        int is32 = __syncthreads_or(odd != 0);
        if (e < N_EDGES) {
            if (is32) {
                g_src[e] = ew[e];
                g_dst[e] = ew[N_EDGES + e];
            } else {
                g_src[e] = ew[2 * e];
                g_dst[e] = ew[2 * (N_EDGES + e)];
            }
        }
        return;
    }
    if (b < NB_DEC + NB_ZERO) {
        int base = (b - NB_DEC) * 4096 + tid;
        float4 z = make_float4(0.f, 0.f, 0.f, 0.f);
#pragma unroll
        for (int w = 0; w < 16; w++) {
            int i = base + w * 256;
            if (i < 3200000)           g_agg4[i] = z;
            else if (i < 3600000)      g_agg24[i - 3200000] = z;
            else if (i < NZ_F4)        g_deg4[i - 3600000] = z;
        }
        return;
    }
    // wconv role: W1 (32768 elems) then W2 (4096 elems)
    int id = (b - NB_DEC - NB_ZERO) * 256 + tid;
    if (id < 2 * 128 * 128) {
        int p = id >> 14, rem = id & 16383;
        int n = rem >> 7, k = rem & 127;
        const float* W = p ? W1r : W1l;
        float w = W[k * 128 + n];                 // W[k][n] -> B[n][k]
        __nv_bfloat16 h = __float2bfloat16(w);
        __nv_bfloat16 l = __float2bfloat16(w - __bfloat162float(h));
        g_Bh_img[p][n * 128 + k] = *(uint16_t*)&h;
        g_Bl_img[p][n * 128 + k] = *(uint16_t*)&l;
    } else if (id < 2 * 128 * 128 + 32 * 128) {
        int p2 = id - 2 * 128 * 128;
        int n = p2 >> 7, k = p2 & 127;
        float w = (n < 16) ? W2l[k * 16 + n] : W2r[k * 16 + (n - 16)];
        __nv_bfloat16 h = __float2bfloat16(w);
        __nv_bfloat16 l = __float2bfloat16(w - __bfloat162float(h));
        g_B2h_img[n * 128 + k] = *(uint16_t*)&h;
        g_B2l_img[n * 128 + k] = *(uint16_t*)&l;
    }
}

// ---------------- kernel 1: batched scatter x[src] -> agg[dst], deg++ -------
// one warp per 8 edges: 8 gathers in flight per warp, then vector-atomic adds
__global__ void __launch_bounds__(256)
scatter1_kernel(const float* __restrict__ x) {
    int gw = (blockIdx.x * 256 + threadIdx.x) >> 5;
    int lane = threadIdx.x & 31;
    int e0 = gw * 8;
    if (e0 >= N_EDGES) return;
    int idx = -1;
    if (lane < 8) {
        int e = e0 + lane;
        if (e < N_EDGES) idx = g_src[e];
    } else if (lane < 16) {
        int e = e0 + lane - 8;
        if (e < N_EDGES) idx = g_dst[e];
    }
    int ss[8], dd[8];
#pragma unroll
    for (int t = 0; t < 8; t++) {
        ss[t] = __shfl_sync(0xffffffffu, idx, t);
        dd[t] = __shfl_sync(0xffffffffu, idx, 8 + t);
    }
    float4 v[8];
#pragma unroll
    for (int t = 0; t < 8; t++)
        if (ss[t] >= 0)
            v[t] = ((const float4*)x)[(size_t)ss[t] * 32 + lane];
#pragma unroll
    for (int t = 0; t < 8; t++)
        if (ss[t] >= 0) {
            atomicAdd(&g_agg4[(size_t)dd[t] * 32 + lane], v[t]);
            if (lane == t) atomicAdd(&g_deg[dd[t]], 1.0f);
        }
}

// ---------------- kernel 2: h = relu((agg*invd)@W1l + b1 + x@W1r) -----------
// mma.sync bf16 3-term split GEMM. CTA = 64x128 tile, 2 CTAs/SM, ldmatrix.
__global__ void __launch_bounds__(256, 2)
gemm1_kernel(const float* __restrict__ x, const float* __restrict__ b1) {
    extern __shared__ __align__(16) char sm[];
    __shared__ float s_bias[128];
    __shared__ float s_invd[64];

    int tid = threadIdx.x, wid = tid >> 5, lane = tid & 31;
    int qr = lane >> 2, qc = lane & 3;
    int row0 = blockIdx.x * 64;
    int r0 = (wid & 3) * 16;
    int c0 = (wid >> 2) * 64;

    if (tid < 128) s_bias[tid] = b1[tid];
    if (tid < 64) {
        int gi = row0 + tid;
        float dg = (gi < N_NODES) ? g_deg[gi] : 1.0f;
        s_invd[tid] = 1.0f / fmaxf(dg, 1.0f);
    }

    uint32_t smb = smem_u32(sm);
    uint32_t a_base = smb +
        (uint32_t)((r0 + ((lane >> 3) & 1) * 8 + (lane & 7)) * ROWB
                   + ((lane >> 4) & 1) * 16);
    uint32_t b_base[4];
#pragma unroll
    for (int p = 0; p < 4; p++)
        b_base[p] = smb +
            (uint32_t)((c0 + 16 * p + ((lane >> 4) & 1) * 8 + (lane & 7)) * ROWB
                       + ((lane >> 3) & 1) * 16);

    float d[8][4];
#pragma unroll
    for (int nj = 0; nj < 8; nj++)
#pragma unroll
        for (int v = 0; v < 4; v++) d[nj][v] = 0.f;

#pragma unroll 1
    for (int phase = 0; phase < 2; phase++) {
        __syncthreads();

        for (int f = tid; f < 64 * 32; f += 256) {
            int r = f >> 5, q = f & 31;
            int gi = row0 + r;
            float4 v = make_float4(0.f, 0.f, 0.f, 0.f);
            if (gi < N_NODES) {
                if (phase == 0) {
                    v = g_agg4[(size_t)gi * 32 + q];
                    float s = s_invd[r];
                    v.x *= s; v.y *= s; v.z *= s; v.w *= s;
                } else {
                    v = ((const float4*)(x + (size_t)gi * 128))[q];
                }
            }
            __nv_bfloat16 h0 = __float2bfloat16(v.x), h1 = __float2bfloat16(v.y);
            __nv_bfloat16 h2 = __float2bfloat16(v.z), h3 = __float2bfloat16(v.w);
            __nv_bfloat16 l0 = __float2bfloat16(v.x - __bfloat162float(h0));
            __nv_bfloat16 l1 = __float2bfloat16(v.y - __bfloat162float(h1));
            __nv_bfloat16 l2 = __float2bfloat16(v.z - __bfloat162float(h2));
            __nv_bfloat16 l3 = __float2bfloat16(v.w - __bfloat162float(h3));
            uint64_t hp = (uint64_t)(*(uint16_t*)&h0)
                        | ((uint64_t)(*(uint16_t*)&h1) << 16)
                        | ((uint64_t)(*(uint16_t*)&h2) << 32)
                        | ((uint64_t)(*(uint16_t*)&h3) << 48);
            uint64_t lp = (uint64_t)(*(uint16_t*)&l0)
                        | ((uint64_t)(*(uint16_t*)&l1) << 16)
                        | ((uint64_t)(*(uint16_t*)&l2) << 32)
                        | ((uint64_t)(*(uint16_t*)&l3) << 48);
            int off = r * ROWB + q * 8;
            *(uint64_t*)(sm + OFF_AH + off) = hp;
            *(uint64_t*)(sm + OFF_AL + off) = lp;
        }
        for (int i = tid; i < 2048; i += 256) {
            int r = i >> 4, w = i & 15;
            int dst = r * ROWB + w * 16;
            *(float4*)(sm + OFF_BH + dst) = ((const float4*)g_Bh_img[phase])[i];
            *(float4*)(sm + OFF_BL + dst) = ((const float4*)g_Bl_img[phase])[i];
        }
        __syncthreads();

#pragma unroll 1
        for (int ks = 0; ks < 8; ks++) {
            uint32_t kadv = (uint32_t)(ks * 32);
            uint32_t ah[4], al[4];
            ldsm4(ah, a_base + OFF_AH + kadv);
            ldsm4(al, a_base + OFF_AL + kadv);
            uint32_t bh[4][4], bl[4][4];
#pragma unroll
            for (int p = 0; p < 4; p++) {
                ldsm4(bh[p], b_base[p] + OFF_BH + kadv);
                ldsm4(bl[p], b_base[p] + OFF_BL + kadv);
            }
#pragma unroll
            for (int p = 0; p < 4; p++) {
                mma_bf16(d[2 * p],     ah, &bh[p][0]);
                mma_bf16(d[2 * p],     al, &bh[p][0]);
                mma_bf16(d[2 * p],     ah, &bl[p][0]);
                mma_bf16(d[2 * p + 1], ah, &bh[p][2]);
                mma_bf16(d[2 * p + 1], al, &bh[p][2]);
                mma_bf16(d[2 * p + 1], ah, &bl[p][2]);
            }
        }
    }

    {
        int rlo = row0 + r0 + qr;
        int rhi = rlo + 8;
#pragma unroll
        for (int nj = 0; nj < 8; nj++) {
            int gc = c0 + nj * 8 + 2 * qc;
            float b0v = s_bias[gc], b1v = s_bias[gc + 1];
            if (rlo < N_NODES) {
                float2 o;
                o.x = fmaxf(d[nj][0] + b0v, 0.f);
                o.y = fmaxf(d[nj][1] + b1v, 0.f);
                *(float2*)(g_h + (size_t)rlo * 128 + gc) = o;
            }
            if (rhi < N_NODES) {
                float2 o;
                o.x = fmaxf(d[nj][2] + b0v, 0.f);
                o.y = fmaxf(d[nj][3] + b1v, 0.f);
                *(float2*)(g_h + (size_t)rhi * 128 + gc) = o;
            }
        }
    }
}

// ---------------- kernel 3: [t|r] = h @ [W2l|W2r] (mma.sync bf16) -----------
// CTA = 64 rows x 32 cols, K=128, 8 warps (4m x 2n), warp tile 16x16.
// cols 0..15 -> g_t, cols 16..31 -> out staging.
__global__ void __launch_bounds__(256)
gemm2_kernel(float* __restrict__ outr) {
    extern __shared__ __align__(16) char sm[];
    int tid = threadIdx.x, wid = tid >> 5, lane = tid & 31;
    int qr = lane >> 2, qc = lane & 3;
    int row0 = blockIdx.x * 64;
    int r0 = (wid & 3) * 16;
    int c0 = (wid >> 2) * 16;

    uint32_t smb = smem_u32(sm);
    uint32_t a_base = smb +
        (uint32_t)((r0 + ((lane >> 3) & 1) * 8 + (lane & 7)) * ROWB
                   + ((lane >> 4) & 1) * 16);
    uint32_t b_base = smb +
        (uint32_t)((c0 + ((lane >> 4) & 1) * 8 + (lane & 7)) * ROWB
                   + ((lane >> 3) & 1) * 16);

    // A conversion: h fp32 -> bf16 hi/lo panels
    for (int f = tid; f < 64 * 32; f += 256) {
        int r = f >> 5, q = f & 31;
        int gi = row0 + r;
        float4 v = (gi < N_NODES) ? g_h4[(size_t)gi * 32 + q]
                                  : make_float4(0.f, 0.f, 0.f, 0.f);
        __nv_bfloat16 h0 = __float2bfloat16(v.x), h1 = __float2bfloat16(v.y);
        __nv_bfloat16 h2 = __float2bfloat16(v.z), h3 = __float2bfloat16(v.w);
        __nv_bfloat16 l0 = __float2bfloat16(v.x - __bfloat162float(h0));
        __nv_bfloat16 l1 = __float2bfloat16(v.y - __bfloat162float(h1));
        __nv_bfloat16 l2 = __float2bfloat16(v.z - __bfloat162float(h2));
        __nv_bfloat16 l3 = __float2bfloat16(v.w - __bfloat162float(h3));
        uint64_t hp = (uint64_t)(*(uint16_t*)&h0)
                    | ((uint64_t)(*(uint16_t*)&h1) << 16)
                    | ((uint64_t)(*(uint16_t*)&h2) << 32)
                    | ((uint64_t)(*(uint16_t*)&h3) << 48);
        uint64_t lp = (uint64_t)(*(uint16_t*)&l0)
                    | ((uint64_t)(*(uint16_t*)&l1) << 16)
                    | ((uint64_t)(*(uint16_t*)&l2) << 32)
                    | ((uint64_t)(*(uint16_t*)&l3) << 48);
        int off = r * ROWB + q * 8;
        *(uint64_t*)(sm + OFF2_AH + off) = hp;
        *(uint64_t*)(sm + OFF2_AL + off) = lp;
    }
    // B copy: 32 rows x 16 float4
    for (int i = tid; i < 512; i += 256) {
        int r = i >> 4, w = i & 15;
        int dst = r * ROWB + w * 16;
        *(float4*)(sm + OFF2_BH + dst) = ((const float4*)g_B2h_img)[i];
        *(float4*)(sm + OFF2_BL + dst) = ((const float4*)g_B2l_img)[i];
    }
    __syncthreads();

    float d[2][4];
#pragma unroll
    for (int nj = 0; nj < 2; nj++)
#pragma unroll
        for (int v = 0; v < 4; v++) d[nj][v] = 0.f;

#pragma unroll 1
    for (int ks = 0; ks < 8; ks++) {
        uint32_t kadv = (uint32_t)(ks * 32);
        uint32_t ah[4], al[4], bh[4], bl[4];
        ldsm4(ah, a_base + OFF2_AH + kadv);
        ldsm4(al, a_base + OFF2_AL + kadv);
        ldsm4(bh, b_base + OFF2_BH + kadv);
        ldsm4(bl, b_base + OFF2_BL + kadv);
        mma_bf16(d[0], ah, &bh[0]);
        mma_bf16(d[0], al, &bh[0]);
        mma_bf16(d[0], ah, &bl[0]);
        mma_bf16(d[1], ah, &bh[2]);
        mma_bf16(d[1], al, &bh[2]);
        mma_bf16(d[1], ah, &bl[2]);
    }

    // epilogue: cols 0..15 -> g_t, 16..31 -> out staging
    {
        int rlo = row0 + r0 + qr;
        int rhi = rlo + 8;
#pragma unroll
        for (int nj = 0; nj < 2; nj++) {
            int gc = c0 + nj * 8 + 2 * qc;
            float* dst_lo;
            float* dst_hi;
            if (gc < 16) {
                dst_lo = g_t   + (size_t)rlo * CLS + gc;
                dst_hi = g_t   + (size_t)rhi * CLS + gc;
            } else {
                dst_lo = outr + (size_t)rlo * CLS + (gc - 16);
                dst_hi = outr + (size_t)rhi * CLS + (gc - 16);
            }
            if (rlo < N_NODES) *(float2*)dst_lo = make_float2(d[nj][0], d[nj][1]);
            if (rhi < N_NODES) *(float2*)dst_hi = make_float2(d[nj][2], d[nj][3]);
        }
    }
}

// ---------------- kernel 4: scatter t[src] -> agg2[dst] (16 floats/edge) ----
__global__ void __launch_bounds__(256)
scatter2_kernel() {
    int idx = blockIdx.x * blockDim.x + threadIdx.x;
    int e = idx >> 2;
    if (e >= N_EDGES) return;
    int l = idx & 3;
    int s = g_src[e];
    int d = g_dst[e];
    float4 v = g_t4[(size_t)s * (CLS / 4) + l];
    atomicAdd(&g_agg24[(size_t)d * (CLS / 4) + l], v);
}

// ---------------- kernel 5: out = log_softmax(r + b2 + agg2/deg) ------------
__global__ void __launch_bounds__(256)
final_kernel(float* __restrict__ out, const float* __restrict__ b2) {
    int idx = blockIdx.x * blockDim.x + threadIdx.x;
    int row = idx >> 4;
    int c = idx & 15;
    if (row >= N_NODES) return;
    float invd = 1.0f / fmaxf(g_deg[row], 1.0f);
    float v = out[(size_t)row * CLS + c] + b2[c]
            + g_agg2[(size_t)row * CLS + c] * invd;
    float m = v;
#pragma unroll
    for (int o = 8; o > 0; o >>= 1)
        m = fmaxf(m, __shfl_xor_sync(0xffffffffu, m, o, 16));
    float e = __expf(v - m);
    float ssum = e;
#pragma unroll
    for (int o = 8; o > 0; o >>= 1)
        ssum += __shfl_xor_sync(0xffffffffu, ssum, o, 16);
    out[(size_t)row * CLS + c] = v - m - __logf(ssum);
}

// ---------------- launch ----------------------------------------------------
extern "C" void kernel_launch(void* const* d_in, const int* in_sizes, int n_in,
                              void* d_out, int out_size) {
    const float* x   = (const float*)d_in[0];
    const int*   ew  = (const int*)d_in[1];      // edge_index raw 32-bit words
    const float* W1l = (const float*)d_in[2];
    const float* b1  = (const float*)d_in[3];
    const float* W1r = (const float*)d_in[4];
    const float* W2l = (const float*)d_in[5];
    const float* b2  = (const float*)d_in[6];
    const float* W2r = (const float*)d_in[7];
    float* out = (float*)d_out;

    prep_kernel<<<NB_PREP, 256>>>(ew, W1l, W1r, W2l, W2r);

    scatter1_kernel<<<(N_EDGES / 8 + 7) / 8, 256>>>(x);   // 75000 warps / 8 per block

    cudaFuncSetAttribute(gemm1_kernel, cudaFuncAttributeMaxDynamicSharedMemorySize,
                         SMEM_G1);
    gemm1_kernel<<<(N_NODES + 63) / 64, 256, SMEM_G1>>>(x, b1);

    cudaFuncSetAttribute(gemm2_kernel, cudaFuncAttributeMaxDynamicSharedMemorySize,
                         SMEM_G2);
    gemm2_kernel<<<(N_NODES + 63) / 64, 256, SMEM_G2>>>(out);

    scatter2_kernel<<<(N_EDGES * 4 + 255) / 256, 256>>>();

    final_kernel<<<(N_NODES * CLS) / 256, 256>>>(out, b2);
}